// round 8
// baseline (speedup 1.0000x reference)
#include <cuda_runtime.h>
#include <stdint.h>

#define BATCH  4
#define NPTS   64
#define DIM    128
#define NFULL  (NPTS*NPTS)     // 4096
#define NPRED  2016            // classes (i<j)
#define NDQ    4               // d-splits in gram64_k
#define DQW    (DIM/NDQ)       // 32
#define KT     32              // k-tile size (63 tiles, 63*32 = 2016)
#define GRID2  (BATCH*32)      // 128 CTAs: (batch, tile-pair m)

__device__ float g_Gp[BATCH][2][NDQ][64*64];   // partial Grams
__device__ double g_acc;
__device__ unsigned int g_done;

// ---------------------------------------------------------------- kernel 1
// Partial 64x64 Gram over a 32-wide d-slice. Grid 32 = (b, tensor, dq).
__global__ __launch_bounds__(256) void gram64_k(const float* __restrict__ student,
                                                const float* __restrict__ teacher) {
    if (blockIdx.x == 0 && threadIdx.x == 0) { g_acc = 0.0; g_done = 0u; }
    int bid = blockIdx.x;
    int b = bid >> 3, t = (bid >> 2) & 1, dq = bid & 3;
    const float* X = (t ? teacher : student) + (size_t)b * NPTS * DIM + dq * DQW;

    __shared__ float sXT[DQW][66];    // transposed slice [d][n], padded
    int tid = threadIdx.x;
    for (int u = tid; u < NPTS * DQW; u += 256) {
        int n = u >> 5, d = u & 31;
        sXT[d][n] = X[(size_t)n * DIM + d];
    }
    __syncthreads();

    int bi = tid >> 4, bj = tid & 15;     // 16x16 grid of 4x4 blocks
    float acc[4][4];
    #pragma unroll
    for (int r = 0; r < 4; r++)
        #pragma unroll
        for (int c = 0; c < 4; c++) acc[r][c] = 0.f;

    #pragma unroll 4
    for (int d = 0; d < DQW; d++) {
        float xi[4], xj[4];
        #pragma unroll
        for (int r = 0; r < 4; r++) xi[r] = sXT[d][bi * 4 + r];
        #pragma unroll
        for (int c = 0; c < 4; c++) xj[c] = sXT[d][bj * 4 + c];
        #pragma unroll
        for (int r = 0; r < 4; r++)
            #pragma unroll
            for (int c = 0; c < 4; c++) acc[r][c] += xi[r] * xj[c];
    }

    float* Gp = g_Gp[b][t][dq];
    #pragma unroll
    for (int r = 0; r < 4; r++)
        #pragma unroll
        for (int c = 0; c < 4; c++)
            Gp[(bi * 4 + r) * 64 + (bj * 4 + c)] = acc[r][c];
}

// ---------------------------------------------------------------- kernel 2
// CTA = (batch, tile-pair m): k-tiles {m, 62-m} (32 kk each), summing
// smooth-L1 over l >= k (weight 2 for l>k, 1 for l==k); final x4 for the
// sign-class multiplicity. A/B rows live in registers (q == lane mod 32),
// Ap broadcast via shfl, rn pair via one conflict-free LDS.64.
__global__ __launch_bounds__(512) void loss_k(float* __restrict__ out) {
    extern __shared__ char sm[];
    float*  sG  = (float*)sm;               // [2][4096]   32 KB
    float2* rn2 = (float2*)(sm + 32768);    // [2048]      16 KB
    float2* sC  = (float2*)(sm + 49152);    // [64][64]    32 KB
    __shared__ float wsum[16];

    int tid = threadIdx.x, wid = tid >> 5, lane = tid & 31;
    int bid = blockIdx.x;
    int b = bid >> 5, m = bid & 31;
    int tA = m, tB = 62 - m;
    int nkk = (tA == tB) ? 32 : 64;

    // --- sum partial Grams (vectorized float4)
    for (int u = tid; u < 2048; u += 512) {       // 2048 float4 = 8192 floats
        int t_ = u >> 10, idx4 = u & 1023;
        float4 s = make_float4(0.f, 0.f, 0.f, 0.f);
        #pragma unroll
        for (int dq = 0; dq < 4; dq++) {
            float4 v = ((const float4*)g_Gp[b][t_][dq])[idx4];
            s.x += v.x; s.y += v.y; s.z += v.z; s.w += v.w;
        }
        ((float4*)sG)[u] = s;
    }
    __syncthreads();

    // --- per-class inverse norms
    #pragma unroll
    for (int c = 0; c < 4; c++) {
        int l = tid + c * 512;
        float2 v = make_float2(0.f, 0.f);
        if (l < NPRED) {
            int p = 0, rem = l;
            while (rem >= 63 - p) { rem -= 63 - p; p++; }
            int q = p + 1 + rem;
            float ss = sG[p * 64 + p] - 2.f * sG[p * 64 + q] + sG[q * 64 + q];
            float st = sG[4096 + p * 64 + p] - 2.f * sG[4096 + p * 64 + q] + sG[4096 + q * 64 + q];
            v.x = 1.f / fmaxf(sqrtf(fmaxf(ss, 0.f)), 1e-12f);
            v.y = 1.f / fmaxf(sqrtf(fmaxf(st, 0.f)), 1e-12f);
        }
        rn2[l] = v;
    }
    __syncthreads();

    // --- per-k scaled difference rows C[kk][p] = ((Gs_ip-Gs_jp)*rns_k, (Gt_ip-Gt_jp)*rnt_k)
    {
        int kkidx = tid >> 3;
        int p0 = (tid & 7) * 8;
        if (kkidx < nkk) {
            int tile = (kkidx < 32) ? tA : tB;
            int k = tile * KT + (kkidx & 31);
            int i = 0, rem = k;
            while (rem >= 63 - i) { rem -= 63 - i; i++; }
            int j = i + 1 + rem;
            float2 rk = rn2[k];
            #pragma unroll
            for (int pp = 0; pp < 8; pp++) {
                int p = p0 + pp;
                sC[kkidx * 64 + p] = make_float2(
                    (sG[i * 64 + p] - sG[j * 64 + p]) * rk.x,
                    (sG[4096 + i * 64 + p] - sG[4096 + j * 64 + p]) * rk.y);
            }
        }
    }
    __syncthreads();

    // --- main loop
    float lsum = 0.f;
    #pragma unroll
    for (int kkb = 0; kkb < 64; kkb += 16) {
        int kkidx = kkb + wid;
        if (kkidx >= nkk) continue;            // warp-uniform
        int tile = (kkidx < 32) ? tA : tB;
        int k = tile * KT + (kkidx & 31);
        float2 c0 = sC[kkidx * 64 + lane];       // q = lane
        float2 c1 = sC[kkidx * 64 + 32 + lane];  // q = 32 + lane
        int l = 0;
        for (int p = 0; p < 63; p++) {
            int rowlen = 63 - p;
            if (l + rowlen <= k) { l += rowlen; continue; }   // whole row below k
            float2 cc = (p < 32) ? c0 : c1;
            float cpx = __shfl_sync(0xffffffffu, cc.x, p & 31);
            float cpy = __shfl_sync(0xffffffffu, cc.y, p & 31);
            int base = l - p - 1;
            if (p < 31) {                        // pass q = lane (q in (p,32))
                int q = lane;
                int lq = base + q;
                bool valid = (q > p) && (lq >= k);
                float w = valid ? ((lq == k) ? 1.f : 2.f) : 0.f;
                float2 rl = rn2[valid ? lq : 0];
                float s = (cpx - c0.x) * rl.x;
                float tt = (cpy - c0.y) * rl.y;
                float d = s - tt, ad = fabsf(d);
                lsum += w * ((ad < 1.f) ? 0.5f * d * d : ad - 0.5f);
            }
            {                                    // pass q = 32 + lane
                int q = 32 + lane;
                int lq = base + q;
                bool valid = (q > p) && (lq >= k);
                float w = valid ? ((lq == k) ? 1.f : 2.f) : 0.f;
                float2 rl = rn2[valid ? lq : 0];
                float s = (cpx - c1.x) * rl.x;
                float tt = (cpy - c1.y) * rl.y;
                float d = s - tt, ad = fabsf(d);
                lsum += w * ((ad < 1.f) ? 0.5f * d * d : ad - 0.5f);
            }
            l += rowlen;
        }
    }

    // --- reduce + finalize
    #pragma unroll
    for (int o = 16; o; o >>= 1) lsum += __shfl_xor_sync(0xffffffffu, lsum, o);
    if (lane == 0) wsum[wid] = lsum;
    __syncthreads();
    if (tid == 0) {
        float s = 0.f;
        #pragma unroll
        for (int w2 = 0; w2 < 16; w2++) s += wsum[w2];
        atomicAdd(&g_acc, (double)s);
        __threadfence();
        unsigned int ticket = atomicAdd(&g_done, 1u);
        if (ticket == GRID2 - 1) {
            double v = *((volatile double*)&g_acc);
            out[0] = (float)(4.0 * v / ((double)BATCH * NFULL * NFULL));
        }
    }
}

extern "C" void kernel_launch(void* const* d_in, const int* in_sizes, int n_in,
                              void* d_out, int out_size) {
    const float* student = (const float*)d_in[0];
    const float* teacher = (const float*)d_in[1];
    cudaFuncSetAttribute(loss_k, cudaFuncAttributeMaxDynamicSharedMemorySize, 81920);
    gram64_k<<<32, 256>>>(student, teacher);
    loss_k<<<GRID2, 512, 81920>>>((float*)d_out);
}

// round 9
// speedup vs baseline: 1.2119x; 1.2119x over previous
#include <cuda_runtime.h>
#include <stdint.h>

#define BATCH  4
#define NPTS   64
#define DIM    128
#define NFULL  (NPTS*NPTS)     // 4096
#define NPRED  2016            // classes (i<j)
#define NDQ    4               // d-splits in gram64_k
#define DQW    (DIM/NDQ)       // 32
#define GRID_L 1008            // loss CTAs: 4 batches x 252

__device__ float g_Gp[BATCH][2][NDQ][64*64];   // partial Grams
__device__ float g_rn[BATCH*2*NPRED];          // [b][t][l] inverse norms
__device__ float g_C [(size_t)BATCH*2*NPRED*64]; // [b][t][k][p] scaled diff rows
__device__ double g_acc;
__device__ unsigned int g_done;

// ---------------------------------------------------------------- kernel 1
// Partial 64x64 Gram over a 32-wide d-slice. Grid 32 = (b, tensor, dq).
__global__ __launch_bounds__(256) void gram64_k(const float* __restrict__ student,
                                                const float* __restrict__ teacher) {
    if (blockIdx.x == 0 && threadIdx.x == 0) { g_acc = 0.0; g_done = 0u; }
    int bid = blockIdx.x;
    int b = bid >> 3, t = (bid >> 2) & 1, dq = bid & 3;
    const float* X = (t ? teacher : student) + (size_t)b * NPTS * DIM + dq * DQW;

    __shared__ float sXT[DQW][66];
    int tid = threadIdx.x;
    for (int u = tid; u < NPTS * DQW; u += 256) {
        int n = u >> 5, d = u & 31;
        sXT[d][n] = X[(size_t)n * DIM + d];
    }
    __syncthreads();

    int bi = tid >> 4, bj = tid & 15;
    float acc[4][4];
    #pragma unroll
    for (int r = 0; r < 4; r++)
        #pragma unroll
        for (int c = 0; c < 4; c++) acc[r][c] = 0.f;

    #pragma unroll 4
    for (int d = 0; d < DQW; d++) {
        float xi[4], xj[4];
        #pragma unroll
        for (int r = 0; r < 4; r++) xi[r] = sXT[d][bi * 4 + r];
        #pragma unroll
        for (int c = 0; c < 4; c++) xj[c] = sXT[d][bj * 4 + c];
        #pragma unroll
        for (int r = 0; r < 4; r++)
            #pragma unroll
            for (int c = 0; c < 4; c++) acc[r][c] += xi[r] * xj[c];
    }

    float* Gp = g_Gp[b][t][dq];
    #pragma unroll
    for (int r = 0; r < 4; r++)
        #pragma unroll
        for (int c = 0; c < 4; c++)
            Gp[(bi * 4 + r) * 64 + (bj * 4 + c)] = acc[r][c];
}

// ---------------------------------------------------------------- kernel 2
// Grid 64 = (b, t, s8). Sum partial Grams -> smem G; compute rn + C for the
// 252-row slice s; write to global.
__global__ __launch_bounds__(256) void prep_k() {
    __shared__ float G[64 * 64];
    __shared__ float sRNl[252];
    __shared__ int   sI[252], sJ[252];

    int bid = blockIdx.x;
    int b = bid >> 4, t = (bid >> 3) & 1, s = bid & 7;
    int tid = threadIdx.x;

    // sum 4 d-partials (float4 vectorized)
    for (int u = tid; u < 1024; u += 256) {
        float4 a = make_float4(0.f, 0.f, 0.f, 0.f);
        #pragma unroll
        for (int dq = 0; dq < NDQ; dq++) {
            float4 v = ((const float4*)g_Gp[b][t][dq])[u];
            a.x += v.x; a.y += v.y; a.z += v.z; a.w += v.w;
        }
        ((float4*)G)[u] = a;
    }
    __syncthreads();

    // rn + (i,j) for slice rows
    if (tid < 252) {
        int l = s * 252 + tid;
        int p = 0, rem = l;
        while (rem >= 63 - p) { rem -= 63 - p; p++; }
        int q = p + 1 + rem;
        float ss = G[p * 64 + p] - 2.f * G[p * 64 + q] + G[q * 64 + q];
        float rn = 1.f / fmaxf(sqrtf(fmaxf(ss, 0.f)), 1e-12f);
        sI[tid] = p; sJ[tid] = q; sRNl[tid] = rn;
        g_rn[(b * 2 + t) * NPRED + l] = rn;
    }
    __syncthreads();

    // C rows for the slice
    for (int u = tid; u < 252 * 64; u += 256) {
        int kl = u >> 6, p = u & 63;
        float val = (G[sI[kl] * 64 + p] - G[sJ[kl] * 64 + p]) * sRNl[kl];
        g_C[((size_t)(b * 2 + t) * NPRED + s * 252 + kl) * 64 + p] = val;
    }
}

// ---------------------------------------------------------------- kernel 3
// Grid 1008 = (b, c252), 128 threads (4 warps). Warp handles k-rows
// {c*4+wid, 2015-(c*4+wid)}; for each, sums smooth-L1 over classes l >= k
// (uniform weight 2; the l==k diagonal double-count is ~1e-12, negligible).
__global__ __launch_bounds__(128) void loss_k(float* __restrict__ out) {
    __shared__ float2 sRNbuf[2017];          // [0] = guard for index -1
    __shared__ float wsum[4];
    float2* sRN = sRNbuf + 1;

    int tid = threadIdx.x, wid = tid >> 5, lane = tid & 31;
    int bid = blockIdx.x;
    int b = bid / 252, c = bid - b * 252;

    const float* rns = g_rn + (b * 2 + 0) * NPRED;
    const float* rnt = g_rn + (b * 2 + 1) * NPRED;
    for (int u = tid; u < NPRED; u += 128)
        sRN[u] = make_float2(rns[u], rnt[u]);
    if (tid == 0) sRNbuf[0] = make_float2(0.f, 0.f);
    __syncthreads();

    float lsum = 0.f;
    #pragma unroll
    for (int rr = 0; rr < 2; rr++) {
        int k = (rr == 0) ? (c * 4 + wid) : (2015 - (c * 4 + wid));
        int i = 0, rem = k;
        while (rem >= 63 - i) { rem -= 63 - i; i++; }
        int j = i + 1 + rem;

        const float* Cs = g_C + ((size_t)(b * 2 + 0) * NPRED + k) * 64;
        const float* Ct = g_C + ((size_t)(b * 2 + 1) * NPRED + k) * 64;
        float c0x = Cs[lane], c1x = Cs[lane + 32];
        float c0y = Ct[lane], c1y = Ct[lane + 32];

        int lo = j;                       // first row: q >= j ; after: q >= p+1
        for (int p = i; p < 63; p++) {
            float sx = (p < 32) ? c0x : c1x;
            float sy = (p < 32) ? c0y : c1y;
            float cpx = __shfl_sync(0xffffffffu, sx, p & 31);
            float cpy = __shfl_sync(0xffffffffu, sy, p & 31);
            int base = 63 * p - ((p * (p - 1)) >> 1) - p - 1;  // + q -> l index
            if (p < 31) {                 // pass q = lane
                float2 rl = sRN[base + lane];
                float d = (cpx - c0x) * rl.x - (cpy - c0y) * rl.y;
                float ad = fabsf(d);
                float m = fminf(ad, 1.f);
                if (lane >= lo) lsum += m * (ad - 0.5f * m);
            }
            {                             // pass q = 32 + lane
                float2 rl = sRN[base + 32 + lane];
                float d = (cpx - c1x) * rl.x - (cpy - c1y) * rl.y;
                float ad = fabsf(d);
                float m = fminf(ad, 1.f);
                if (lane + 32 >= lo) lsum += m * (ad - 0.5f * m);
            }
            lo = p + 2;
        }
    }

    #pragma unroll
    for (int o = 16; o; o >>= 1) lsum += __shfl_xor_sync(0xffffffffu, lsum, o);
    if (lane == 0) wsum[wid] = lsum;
    __syncthreads();
    if (tid == 0) {
        float sblk = wsum[0] + wsum[1] + wsum[2] + wsum[3];
        atomicAdd(&g_acc, (double)(2.0f * sblk));   // weight 2 for l>k (diag ~0)
        __threadfence();
        unsigned int ticket = atomicAdd(&g_done, 1u);
        if (ticket == GRID_L - 1) {
            double v = *((volatile double*)&g_acc);
            out[0] = (float)(4.0 * v / ((double)BATCH * NFULL * NFULL));
        }
    }
}

extern "C" void kernel_launch(void* const* d_in, const int* in_sizes, int n_in,
                              void* d_out, int out_size) {
    const float* student = (const float*)d_in[0];
    const float* teacher = (const float*)d_in[1];
    gram64_k<<<32, 256>>>(student, teacher);
    prep_k<<<64, 256>>>();
    loss_k<<<GRID_L, 128>>>((float*)d_out);
}

// round 10
// speedup vs baseline: 1.2192x; 1.0060x over previous
#include <cuda_runtime.h>
#include <stdint.h>

#define BATCH  4
#define NPTS   64
#define DIM    128
#define NFULL  (NPTS*NPTS)     // 4096
#define NPRED  2016            // classes (i<j)
#define GRID_P 64              // (b, t, slice s of 252 rows)
#define GRID_L 504             // (b, 126 row-groups)

__device__ float g_rn[BATCH*2*NPRED];            // [b][t][l] inverse norms
__device__ float g_C [(size_t)BATCH*2*NPRED*64]; // [b][t][k][p] scaled diff rows
__device__ double g_acc;
__device__ unsigned int g_done;

// ---------------------------------------------------------------- kernel 1
// Grid 64 = (b, t, s). Compute the 64x64 Gram G for (b,t) in-register from
// the raw inputs (4 d-slices), then rn + C rows for slice s (252 k-rows).
__global__ __launch_bounds__(256) void prep_k(const float* __restrict__ student,
                                              const float* __restrict__ teacher) {
    if (blockIdx.x == 0 && threadIdx.x == 0) { g_acc = 0.0; g_done = 0u; }
    int bid = blockIdx.x;
    int b = bid >> 4, t = (bid >> 3) & 1, s = bid & 7;
    const float* X = (t ? teacher : student) + (size_t)b * NPTS * DIM;

    __shared__ float sXT[32][67];    // transposed d-slice, 67-pad: conflict-free
    __shared__ float G[64 * 64];
    __shared__ float sRNl[252];
    __shared__ int   sI[252], sJ[252];

    int tid = threadIdx.x;
    int bi = tid >> 4, bj = tid & 15;

    float acc[4][4];
    #pragma unroll
    for (int r = 0; r < 4; r++)
        #pragma unroll
        for (int c = 0; c < 4; c++) acc[r][c] = 0.f;

    for (int dq = 0; dq < 4; dq++) {
        if (dq) __syncthreads();             // done reading previous slice
        for (int u = tid; u < NPTS * 32; u += 256) {
            int n = u >> 5, d = u & 31;
            sXT[d][n] = X[(size_t)n * DIM + dq * 32 + d];
        }
        __syncthreads();
        #pragma unroll 4
        for (int d = 0; d < 32; d++) {
            float xi[4], xj[4];
            #pragma unroll
            for (int r = 0; r < 4; r++) xi[r] = sXT[d][bi * 4 + r];
            #pragma unroll
            for (int c = 0; c < 4; c++) xj[c] = sXT[d][bj * 4 + c];
            #pragma unroll
            for (int r = 0; r < 4; r++)
                #pragma unroll
                for (int c = 0; c < 4; c++) acc[r][c] += xi[r] * xj[c];
        }
    }
    #pragma unroll
    for (int r = 0; r < 4; r++)
        #pragma unroll
        for (int c = 0; c < 4; c++)
            G[(bi * 4 + r) * 64 + (bj * 4 + c)] = acc[r][c];
    __syncthreads();

    // rn + (i,j) for this slice's 252 rows
    if (tid < 252) {
        int l = s * 252 + tid;
        int p = 0, rem = l;
        while (rem >= 63 - p) { rem -= 63 - p; p++; }
        int q = p + 1 + rem;
        float ss = G[p * 64 + p] - 2.f * G[p * 64 + q] + G[q * 64 + q];
        float rn = 1.f / fmaxf(sqrtf(fmaxf(ss, 0.f)), 1e-12f);
        sI[tid] = p; sJ[tid] = q; sRNl[tid] = rn;
        g_rn[(b * 2 + t) * NPRED + l] = rn;
    }
    __syncthreads();

    // C rows for the slice: C[k][p] = (G[i_k,p] - G[j_k,p]) * rn_k
    for (int u = tid; u < 252 * 64; u += 256) {
        int kl = u >> 6, p = u & 63;
        float val = (G[sI[kl] * 64 + p] - G[sJ[kl] * 64 + p]) * sRNl[kl];
        g_C[((size_t)(b * 2 + t) * NPRED + s * 252 + kl) * 64 + p] = val;
    }
}

// ---------------------------------------------------------------- kernel 2
// Grid 504 = (b, c126), 256 threads (8 warps). Warp w owns balanced k-row
// pair {c*8+w, 2015-(c*8+w)}; sums smooth-L1 over classes l >= k (uniform
// weight 2; the l==k diagonal term is ~1e-12, negligible). Final x4 for the
// sign-class multiplicity; mean over the full 4096^2 count.
__global__ __launch_bounds__(256) void loss_k(float* __restrict__ out) {
    __shared__ float2 sRNbuf[2017];          // [0] = guard for index -1
    __shared__ float wsum[8];
    float2* sRN = sRNbuf + 1;

    int tid = threadIdx.x, wid = tid >> 5, lane = tid & 31;
    int bid = blockIdx.x;
    int b = bid / 126, c = bid - b * 126;

    const float* rns = g_rn + (b * 2 + 0) * NPRED;
    const float* rnt = g_rn + (b * 2 + 1) * NPRED;
    for (int u = tid; u < NPRED; u += 256)
        sRN[u] = make_float2(rns[u], rnt[u]);
    if (tid == 0) sRNbuf[0] = make_float2(0.f, 0.f);
    __syncthreads();

    float lsum = 0.f;
    #pragma unroll
    for (int rr = 0; rr < 2; rr++) {
        int k = (rr == 0) ? (c * 8 + wid) : (2015 - (c * 8 + wid));
        int i = 0, rem = k;
        while (rem >= 63 - i) { rem -= 63 - i; i++; }
        int j = i + 1 + rem;

        const float* Cs = g_C + ((size_t)(b * 2 + 0) * NPRED + k) * 64;
        const float* Ct = g_C + ((size_t)(b * 2 + 1) * NPRED + k) * 64;
        float c0x = Cs[lane], c1x = Cs[lane + 32];
        float c0y = Ct[lane], c1y = Ct[lane + 32];

        int lo = j;                       // first row: q >= j ; after: q >= p+1
        for (int p = i; p < 63; p++) {
            float sx = (p < 32) ? c0x : c1x;
            float sy = (p < 32) ? c0y : c1y;
            float cpx = __shfl_sync(0xffffffffu, sx, p & 31);
            float cpy = __shfl_sync(0xffffffffu, sy, p & 31);
            int base = 63 * p - ((p * (p - 1)) >> 1) - p - 1;  // + q -> l index
            if (p < 31) {                 // pass q = lane
                float2 rl = sRN[base + lane];
                float d = (cpx - c0x) * rl.x - (cpy - c0y) * rl.y;
                float ad = fabsf(d);
                float m = fminf(ad, 1.f);
                if (lane >= lo) lsum += m * (ad - 0.5f * m);
            }
            {                             // pass q = 32 + lane
                float2 rl = sRN[base + 32 + lane];
                float d = (cpx - c1x) * rl.x - (cpy - c1y) * rl.y;
                float ad = fabsf(d);
                float m = fminf(ad, 1.f);
                if (lane + 32 >= lo) lsum += m * (ad - 0.5f * m);
            }
            lo = p + 2;
        }
    }

    #pragma unroll
    for (int o = 16; o; o >>= 1) lsum += __shfl_xor_sync(0xffffffffu, lsum, o);
    if (lane == 0) wsum[wid] = lsum;
    __syncthreads();
    if (tid == 0) {
        float sblk = 0.f;
        #pragma unroll
        for (int w2 = 0; w2 < 8; w2++) sblk += wsum[w2];
        atomicAdd(&g_acc, (double)(2.0f * sblk));   // weight 2 for l>k
        __threadfence();
        unsigned int ticket = atomicAdd(&g_done, 1u);
        if (ticket == GRID_L - 1) {
            double v = *((volatile double*)&g_acc);
            out[0] = (float)(4.0 * v / ((double)BATCH * NFULL * NFULL));
        }
    }
}

extern "C" void kernel_launch(void* const* d_in, const int* in_sizes, int n_in,
                              void* d_out, int out_size) {
    const float* student = (const float*)d_in[0];
    const float* teacher = (const float*)d_in[1];
    prep_k<<<GRID_P, 256>>>(student, teacher);
    loss_k<<<GRID_L, 256>>>((float*)d_out);
}

// round 12
// speedup vs baseline: 1.2737x; 1.0447x over previous
#include <cuda_runtime.h>
#include <stdint.h>

#define BATCH  4
#define NPTS   64
#define DIM    128
#define NFULL  (NPTS*NPTS)     // 4096
#define NPRED  2016            // classes (i<j)
#define GRID_P 128             // (b, t, slice s of 126 rows)
#define GRID_L 1008            // (b, 252 groups of 4 row-pairs x 2 parity warps)

__device__ float g_rn[BATCH*2*NPRED];            // [b][t][l] inverse norms
__device__ float g_C [(size_t)BATCH*2*NPRED*64]; // [b][t][k][p] scaled diff rows
__device__ double g_acc;
__device__ unsigned int g_done;

// ---------------------------------------------------------------- kernel 1
// Grid 128 = (b, t, s16). Compute the 64x64 Gram G for (b,t) in-register from
// the raw inputs (4 d-slices), then rn + C rows for slice s (126 k-rows).
__global__ __launch_bounds__(256) void prep_k(const float* __restrict__ student,
                                              const float* __restrict__ teacher) {
    if (blockIdx.x == 0 && threadIdx.x == 0) { g_acc = 0.0; g_done = 0u; }
    int bid = blockIdx.x;
    int b = bid >> 5, t = (bid >> 4) & 1, s = bid & 15;
    const float* X = (t ? teacher : student) + (size_t)b * NPTS * DIM;

    __shared__ float sXT[32][67];    // transposed d-slice, padded
    __shared__ float G[64 * 64];
    __shared__ float sRNl[126];
    __shared__ int   sI[126], sJ[126];

    int tid = threadIdx.x;
    int bi = tid >> 4, bj = tid & 15;

    float acc[4][4];
    #pragma unroll
    for (int r = 0; r < 4; r++)
        #pragma unroll
        for (int c = 0; c < 4; c++) acc[r][c] = 0.f;

    for (int dq = 0; dq < 4; dq++) {
        if (dq) __syncthreads();
        for (int u = tid; u < NPTS * 32; u += 256) {
            int n = u >> 5, d = u & 31;
            sXT[d][n] = X[(size_t)n * DIM + dq * 32 + d];
        }
        __syncthreads();
        #pragma unroll 4
        for (int d = 0; d < 32; d++) {
            float xi[4], xj[4];
            #pragma unroll
            for (int r = 0; r < 4; r++) xi[r] = sXT[d][bi * 4 + r];
            #pragma unroll
            for (int c = 0; c < 4; c++) xj[c] = sXT[d][bj * 4 + c];
            #pragma unroll
            for (int r = 0; r < 4; r++)
                #pragma unroll
                for (int c = 0; c < 4; c++) acc[r][c] += xi[r] * xj[c];
        }
    }
    #pragma unroll
    for (int r = 0; r < 4; r++)
        #pragma unroll
        for (int c = 0; c < 4; c++)
            G[(bi * 4 + r) * 64 + (bj * 4 + c)] = acc[r][c];
    __syncthreads();

    if (tid < 126) {
        int l = s * 126 + tid;
        int p = 0, rem = l;
        while (rem >= 63 - p) { rem -= 63 - p; p++; }
        int q = p + 1 + rem;
        float ss = G[p * 64 + p] - 2.f * G[p * 64 + q] + G[q * 64 + q];
        float rn = 1.f / fmaxf(sqrtf(fmaxf(ss, 0.f)), 1e-12f);
        sI[tid] = p; sJ[tid] = q; sRNl[tid] = rn;
        g_rn[(b * 2 + t) * NPRED + l] = rn;
    }
    __syncthreads();

    for (int u = tid; u < 126 * 64; u += 256) {
        int kl = u >> 6, p = u & 63;
        float val = (G[sI[kl] * 64 + p] - G[sJ[kl] * 64 + p]) * sRNl[kl];
        g_C[((size_t)(b * 2 + t) * NPRED + s * 126 + kl) * 64 + p] = val;
    }
}

// ---------------------------------------------------------------- kernel 2
// Grid 1008 = (b, c252), 256 threads (8 warps). Warp w = (pair pr, parity pa):
// pr = w>>1 in 0..3, pa = w&1. Row pair {g, 2015-g} with g = c*4+pr; the
// p-loop of each row is split by parity across the two warps (stride 2).
// At iteration p the valid range is q >= j for p==i, else q >= p+1.
// Uniform weight 2 for l>k (the l==k diagonal term is ~1e-12, negligible);
// final x4 sign-class multiplicity; mean over the full 4096^2 count.
__global__ __launch_bounds__(256) void loss_k(float* __restrict__ out) {
    __shared__ float2 sRNbuf[2017];          // [0] = guard for index -1
    __shared__ float wsum[8];
    float2* sRN = sRNbuf + 1;

    int tid = threadIdx.x, wid = tid >> 5, lane = tid & 31;
    int pr = wid >> 1, pa = wid & 1;
    int bid = blockIdx.x;
    int b = bid / 252, c = bid - b * 252;

    const float* rns = g_rn + (b * 2 + 0) * NPRED;
    const float* rnt = g_rn + (b * 2 + 1) * NPRED;
    for (int u = tid; u < NPRED; u += 256)
        sRN[u] = make_float2(rns[u], rnt[u]);
    if (tid == 0) sRNbuf[0] = make_float2(0.f, 0.f);
    __syncthreads();

    float lsum0 = 0.f, lsum1 = 0.f;
    #pragma unroll
    for (int rr = 0; rr < 2; rr++) {
        int g = c * 4 + pr;
        int k = (rr == 0) ? g : (2015 - g);
        int i = 0, rem = k;
        while (rem >= 63 - i) { rem -= 63 - i; i++; }
        int j = i + 1 + rem;

        const float* Cs = g_C + ((size_t)(b * 2 + 0) * NPRED + k) * 64;
        const float* Ct = g_C + ((size_t)(b * 2 + 1) * NPRED + k) * 64;
        float c0x = Cs[lane], c1x = Cs[lane + 32];
        float c0y = Ct[lane], c1y = Ct[lane + 32];

        for (int p = i + pa; p < 63; p += 2) {
            int lo = (p == i) ? j : (p + 1);   // q >= lo
            float sx = (p < 32) ? c0x : c1x;
            float sy = (p < 32) ? c0y : c1y;
            float cpx = __shfl_sync(0xffffffffu, sx, p & 31);
            float cpy = __shfl_sync(0xffffffffu, sy, p & 31);
            int base = 63 * p - ((p * (p - 1)) >> 1) - p - 1;  // + q -> l index
            if (p < 31) {                 // pass q = lane
                float2 rl = sRN[base + lane];
                float d = (cpx - c0x) * rl.x - (cpy - c0y) * rl.y;
                float ad = fabsf(d);
                float m = fminf(ad, 1.f);
                if (lane >= lo) lsum0 += m * (ad - 0.5f * m);
            }
            {                             // pass q = 32 + lane
                float2 rl = sRN[base + 32 + lane];
                float d = (cpx - c1x) * rl.x - (cpy - c1y) * rl.y;
                float ad = fabsf(d);
                float m = fminf(ad, 1.f);
                if (lane + 32 >= lo) lsum1 += m * (ad - 0.5f * m);
            }
        }
    }

    float lsum = lsum0 + lsum1;
    #pragma unroll
    for (int o = 16; o; o >>= 1) lsum += __shfl_xor_sync(0xffffffffu, lsum, o);
    if (lane == 0) wsum[wid] = lsum;
    __syncthreads();
    if (tid == 0) {
        float sblk = 0.f;
        #pragma unroll
        for (int w2 = 0; w2 < 8; w2++) sblk += wsum[w2];
        atomicAdd(&g_acc, (double)(2.0f * sblk));   // weight 2 for l>k
        __threadfence();
        unsigned int ticket = atomicAdd(&g_done, 1u);
        if (ticket == GRID_L - 1) {
            double v = *((volatile double*)&g_acc);
            out[0] = (float)(4.0 * v / ((double)BATCH * NFULL * NFULL));
        }
    }
}

extern "C" void kernel_launch(void* const* d_in, const int* in_sizes, int n_in,
                              void* d_out, int out_size) {
    const float* student = (const float*)d_in[0];
    const float* teacher = (const float*)d_in[1];
    prep_k<<<GRID_P, 256>>>(student, teacher);
    loss_k<<<GRID_L, 256>>>((float*)d_out);
}